// round 13
// baseline (speedup 1.0000x reference)
#include <cuda_runtime.h>
#include <math.h>
#include <stdint.h>

// ---------------------------------------------------------------------------
// _NLBlock on GB300, legacy mma.sync tf32 (compute_103-safe).
// R11 = R10 + (a) Mt via z-batched split-K (4x K=256) + deterministic reduce,
// (b) chunked logits->softmax->AV->LN pipeline (4 chunks x 2 batches) so the
// memory-bound stages and GEMM tail-waves overlap the next chunk's logits,
// (c) explicit ld (row stride) parameter in the GEMM.
// ---------------------------------------------------------------------------

#define Bv 8
#define Tt 1024
#define Ss 2048
#define Cc 1024

__device__ float g_P     [Bv * Tt * Cc];   // x @ Mt
__device__ float g_giT   [Bv * Cc * Ss];   // gi transposed: [b][c][s]
__device__ float g_logits[Bv * Tt * Ss];
__device__ float g_att   [Bv * Tt * Cc];
__device__ float g_twT   [Cc * Cc];        // theta_w^T
__device__ float g_pwT   [Cc * Cc];        // phi_w^T
__device__ float g_MtP   [4 * Cc * Cc];    // Mt split-K partials
__device__ float g_Mt    [Cc * Cc];        // Mt[c',c] = sum_o phw[o,c'] thw[o,c]
__device__ float g_vp    [32 * Cc];        // vker partials
__device__ float g_v     [Cc];             // v[c'] = sum_o theta_b[o] phi_w[o,c']
__device__ float g_cb    [Bv * Ss];        // 32 * lfb[b,s,:].v

__device__ __forceinline__ uint32_t fu(float f) { return __float_as_uint(f); }

__device__ __forceinline__ float rtf32(float x) {
    uint32_t u;
    asm("cvt.rna.tf32.f32 %0, %1;" : "=r"(u) : "f"(x));
    return __uint_as_float(u);
}

__device__ __forceinline__ uint32_t s2u(const void* p) {
    uint32_t a;
    asm("{ .reg .u64 t; cvta.to.shared.u64 t, %1; cvt.u32.u64 %0, t; }"
        : "=r"(a) : "l"(p));
    return a;
}

__device__ __forceinline__ float lds32(uint32_t a) {
    float v;
    asm volatile("ld.shared.f32 %0, [%1];" : "=f"(v) : "r"(a));
    return v;
}

__device__ __forceinline__ void cpa16(uint32_t s, const void* g) {
    asm volatile("cp.async.cg.shared.global [%0], [%1], 16;"
                 :: "r"(s), "l"(g) : "memory");
}
#define CP_COMMIT() asm volatile("cp.async.commit_group;" ::: "memory")
#define CP_WAIT(n)  asm volatile("cp.async.wait_group %0;" :: "n"(n) : "memory")

__device__ __forceinline__ void mma8(float* d, uint32_t a0, uint32_t a1,
                                     uint32_t a2, uint32_t a3,
                                     uint32_t b0, uint32_t b1) {
    asm("mma.sync.aligned.m16n8k8.row.col.f32.tf32.tf32.f32 "
        "{%0,%1,%2,%3}, {%4,%5,%6,%7}, {%8,%9}, {%0,%1,%2,%3};"
        : "+f"(d[0]), "+f"(d[1]), "+f"(d[2]), "+f"(d[3])
        : "r"(a0), "r"(a1), "r"(a2), "r"(a3), "r"(b0), "r"(b1));
}

constexpr int STAGE = 32768;                    // A 16KB + B 16KB
constexpr int NSTG  = 3;
constexpr int SMEM_ALL = 1024 + NSTG * STAGE;   // 99328; x2 CTAs = 194KB/SM

// ---------------------------------------------------------------------------
// NT GEMM, CTA tile 128x128x32, 256 thr (8 warps: 2M x 4N, 64x32 per warp)
//   SPLIT: hi/lo 3xTF32 at fragment use   TRANS: write C transposed [n][m]
//   C = alpha * A@B^T (+bias[z*sBias + n]) (+res);  ld = A/B row stride,
//   K = contraction length (<= ld for split-K slabs)
// ---------------------------------------------------------------------------
template <bool SPLIT, bool TRANS>
__global__ void __launch_bounds__(256, 2) gemm_cp(
    const float* __restrict__ A, const float* __restrict__ B,
    const float* __restrict__ bias, const float* __restrict__ res,
    float* __restrict__ C,
    int N, int K, int ld, float alpha,
    size_t sA, size_t sB, size_t sC, size_t sBias)
{
    extern __shared__ char sm[];
    const uint32_t sb = s2u(sm);
    const int tid  = threadIdx.x;
    const int lane = tid & 31;
    const int wid  = tid >> 5;
    const int wm   = wid >> 2;
    const int wn   = wid & 3;
    const int n0   = blockIdx.x * 128;

    const float* Ag = A + blockIdx.z * sA + (size_t)blockIdx.y * 128 * ld;
    const float* Bg = B + blockIdx.z * sB + (size_t)n0 * ld;
    float* Cg = C + blockIdx.z * sC;
    const float* Rg = res ? res + blockIdx.z * sC : nullptr;

    float* sbias = (float*)sm;                  // 512 B
    if (bias && tid < 128) sbias[tid] = bias[blockIdx.z * sBias + n0 + tid];

    size_t   goff[4];
    uint32_t soff[4];
#pragma unroll
    for (int i = 0; i < 4; i++) {
        int v = i * 256 + tid;
        int r = v >> 3, c4 = v & 7;
        goff[i] = (size_t)r * ld + c4 * 4;
        soff[i] = (uint32_t)(r * 128 + ((c4 * 16) ^ ((r & 7) << 4)));
    }
    const uint32_t stg0 = sb + 1024;

#define ISSUE(CK)                                                             \
    {                                                                         \
        uint32_t st = stg0 + ((CK) % NSTG) * STAGE;                           \
        int k0 = (CK) * 32;                                                   \
        _Pragma("unroll")                                                     \
        for (int i = 0; i < 4; i++)                                           \
            cpa16(st + soff[i], Ag + goff[i] + k0);                           \
        _Pragma("unroll")                                                     \
        for (int i = 0; i < 4; i++)                                           \
            cpa16(st + 16384 + soff[i], Bg + goff[i] + k0);                   \
        CP_COMMIT();                                                          \
    }

    float acc[4][4][4];
#pragma unroll
    for (int mt = 0; mt < 4; mt++)
#pragma unroll
        for (int nt = 0; nt < 4; nt++)
#pragma unroll
            for (int e = 0; e < 4; e++) acc[mt][nt][e] = 0.f;

    const int NC = K / 32;
    ISSUE(0);
    ISSUE(1);

    const uint32_t cB = (uint32_t)(lane & 3) * 4;
    const int      rq = lane >> 2;

    for (int ck = 0; ck < NC; ck++) {
        if (ck + 1 < NC) { CP_WAIT(1); } else { CP_WAIT(0); }
        __syncthreads();
        if (ck + 2 < NC) ISSUE(ck + 2);

        const uint32_t AS = stg0 + (ck % NSTG) * STAGE;
        const uint32_t BS = AS + 16384;

#pragma unroll
        for (int j = 0; j < 4; j++) {
            const uint32_t jb = (uint32_t)(j * 32) + cB;

            float bh[4][2], bl[4][2];
#pragma unroll
            for (int nt = 0; nt < 4; nt++) {
                int row = wn * 32 + nt * 8 + rq;
                uint32_t rb = BS + row * 128;
                uint32_t sw = (uint32_t)((row & 7) << 4);
#pragma unroll
                for (int p = 0; p < 2; p++) {
                    float x = lds32(rb + ((jb + (uint32_t)(p * 16)) ^ sw));
                    if (SPLIT) {
                        float h = __uint_as_float(fu(x) & 0xFFFFE000u);
                        bh[nt][p] = h; bl[nt][p] = x - h;
                    } else {
                        bh[nt][p] = rtf32(x);
                    }
                }
            }
#pragma unroll
            for (int mt = 0; mt < 4; mt++) {
                float ah[2][2], al[2][2];
#pragma unroll
                for (int rr = 0; rr < 2; rr++) {
                    int row = wm * 64 + mt * 16 + rq + rr * 8;
                    uint32_t rb = AS + row * 128;
                    uint32_t sw = (uint32_t)((row & 7) << 4);
#pragma unroll
                    for (int p = 0; p < 2; p++) {
                        float x = lds32(rb + ((jb + (uint32_t)(p * 16)) ^ sw));
                        if (SPLIT) {
                            float h = __uint_as_float(fu(x) & 0xFFFFE000u);
                            ah[rr][p] = h; al[rr][p] = x - h;
                        } else {
                            ah[rr][p] = rtf32(x);
                        }
                    }
                }
                uint32_t aH0 = fu(ah[0][0]), aH1 = fu(ah[1][0]);
                uint32_t aH2 = fu(ah[0][1]), aH3 = fu(ah[1][1]);
                uint32_t aL0 = 0, aL1 = 0, aL2 = 0, aL3 = 0;
                if (SPLIT) {
                    aL0 = fu(al[0][0]); aL1 = fu(al[1][0]);
                    aL2 = fu(al[0][1]); aL3 = fu(al[1][1]);
                }
#pragma unroll
                for (int nt = 0; nt < 4; nt++) {
                    uint32_t bH0 = fu(bh[nt][0]), bH1 = fu(bh[nt][1]);
                    mma8(acc[mt][nt], aH0, aH1, aH2, aH3, bH0, bH1);
                    if (SPLIT) {
                        uint32_t bL0 = fu(bl[nt][0]);
                        uint32_t bL1 = fu(bl[nt][1]);
                        mma8(acc[mt][nt], aL0, aL1, aL2, aL3, bH0, bH1);
                        mma8(acc[mt][nt], aH0, aH1, aH2, aH3, bL0, bL1);
                    }
                }
            }
        }
    }

    if (!TRANS) {
#pragma unroll
        for (int mt = 0; mt < 4; mt++) {
            size_t m0 = (size_t)blockIdx.y * 128 + wm * 64 + mt * 16 + rq;
#pragma unroll
            for (int nt = 0; nt < 4; nt++) {
                int cl = wn * 32 + nt * 8 + (lane & 3) * 2;
                int col = n0 + cl;
                float v0 = acc[mt][nt][0] * alpha, v1 = acc[mt][nt][1] * alpha;
                float v2 = acc[mt][nt][2] * alpha, v3 = acc[mt][nt][3] * alpha;
                if (bias) {
                    float b0 = sbias[cl], b1 = sbias[cl + 1];
                    v0 += b0; v1 += b1; v2 += b0; v3 += b1;
                }
                size_t i0 = m0 * N + col, i1 = (m0 + 8) * N + col;
                if (Rg) {
                    v0 += Rg[i0]; v1 += Rg[i0 + 1];
                    v2 += Rg[i1]; v3 += Rg[i1 + 1];
                }
                float2 w0; w0.x = v0; w0.y = v1;
                float2 w1; w1.x = v2; w1.y = v3;
                *(float2*)(Cg + i0) = w0;
                *(float2*)(Cg + i1) = w1;
            }
        }
    } else {
        __syncthreads();                       // stages dead, reuse as buffer
        float* tb = (float*)(sm + 1024);
#pragma unroll
        for (int mt = 0; mt < 4; mt++) {
            int ml = wm * 64 + mt * 16 + rq;
#pragma unroll
            for (int nt = 0; nt < 4; nt++) {
                int cl = wn * 32 + nt * 8 + (lane & 3) * 2;
                float v0 = acc[mt][nt][0] * alpha, v1 = acc[mt][nt][1] * alpha;
                float v2 = acc[mt][nt][2] * alpha, v3 = acc[mt][nt][3] * alpha;
                if (bias) {
                    float b0 = sbias[cl], b1 = sbias[cl + 1];
                    v0 += b0; v1 += b1; v2 += b0; v3 += b1;
                }
                tb[cl * 132 + ml]           = v0;
                tb[(cl + 1) * 132 + ml]     = v1;
                tb[cl * 132 + ml + 8]       = v2;
                tb[(cl + 1) * 132 + ml + 8] = v3;
            }
        }
        __syncthreads();
        size_t mg_base = (size_t)blockIdx.y * 128 + lane * 4;
        size_t b  = mg_base >> 11;
        size_t s  = mg_base & 2047;
        float* Ct = C + b * (size_t)Cc * Ss + s;
#pragma unroll
        for (int rr = 0; rr < 16; rr++) {
            int n = wid * 16 + rr;
            float4 v = *(const float4*)(tb + n * 132 + lane * 4);
            *(float4*)(Ct + (size_t)(n0 + n) * Ss) = v;
        }
    }
#undef ISSUE
}

// ---------------------------------------------------------------------------
__global__ void __launch_bounds__(256) transpose_k(
    const float* __restrict__ in, float* __restrict__ out)
{
    __shared__ float t[32][33];
    int x = blockIdx.x * 32 + threadIdx.x;
    int y = blockIdx.y * 32 + threadIdx.y;
#pragma unroll
    for (int i = 0; i < 32; i += 8)
        t[threadIdx.y + i][threadIdx.x] = in[(size_t)(y + i) * Cc + x];
    __syncthreads();
    x = blockIdx.y * 32 + threadIdx.x;
    y = blockIdx.x * 32 + threadIdx.y;
#pragma unroll
    for (int i = 0; i < 32; i += 8)
        out[(size_t)(y + i) * Cc + x] = t[threadIdx.x][threadIdx.y + i];
}

// Mt split-K reduce: Mt[i] = sum_{z<4} MtP[z][i]
__global__ void __launch_bounds__(256) red4_k(
    const float* __restrict__ in, float* __restrict__ out)
{
    size_t i = (size_t)blockIdx.x * 256 + threadIdx.x;
    out[i] = (in[i] + in[i + 1048576]) + (in[i + 2097152] + in[i + 3145728]);
}

// vker phase 1: vp[oc][c] = sum_{o in chunk oc} tb[o]*pw[o*C+c]
__global__ void __launch_bounds__(256) vker_part(
    const float* __restrict__ tb, const float* __restrict__ pw,
    float* __restrict__ vp)
{
    int c = blockIdx.x * 256 + threadIdx.x;
    int o0 = blockIdx.y * 32;
    float s = 0.f;
#pragma unroll
    for (int i = 0; i < 32; i++)
        s = fmaf(tb[o0 + i], pw[(size_t)(o0 + i) * Cc + c], s);
    vp[(size_t)blockIdx.y * Cc + c] = s;
}
__global__ void __launch_bounds__(256) vker_red(
    const float* __restrict__ vp, float* __restrict__ v)
{
    int c = blockIdx.x * 256 + threadIdx.x;
    float s = 0.f;
#pragma unroll
    for (int i = 0; i < 32; i++) s += vp[(size_t)i * Cc + c];
    v[c] = s;
}

// cb[row] = 32 * dot(lfb[row,:], v) ; warp per row, 8 rows per block
__global__ void __launch_bounds__(256) cbias_k(
    const float* __restrict__ lfb, const float* __restrict__ v,
    float* __restrict__ cb)
{
    const int lane = threadIdx.x & 31;
    const int w    = threadIdx.x >> 5;
    const size_t row = (size_t)blockIdx.x * 8 + w;
    const float* p = lfb + row * Cc;
    float s = 0.f;
#pragma unroll
    for (int i = 0; i < 32; i++) {
        int c = i * 32 + lane;
        s = fmaf(p[c], v[c], s);
    }
#pragma unroll
    for (int o = 16; o; o >>= 1) s += __shfl_xor_sync(0xffffffffu, s, o);
    if (lane == 0) cb[row] = 32.0f * s;
}

// ---------------------------------------------------------------------------
__device__ __forceinline__ float fexp(float x) {
    float t = fmaxf(x * 1.4426950408889634f, -126.f);
    float n = rintf(t);
    float f = t - n;
    float p = 0.0013333558f;
    p = fmaf(p, f, 0.0096181291f);
    p = fmaf(p, f, 0.0555041087f);
    p = fmaf(p, f, 0.2402265069f);
    p = fmaf(p, f, 0.6931471806f);
    p = fmaf(p, f, 1.0f);
    return p * __int_as_float(((int)n + 127) << 23);
}

__global__ void __launch_bounds__(256) softmax_k(float* __restrict__ logits) {
    float4* p = (float4*)(logits + (size_t)blockIdx.x * Ss);
    const int tid = threadIdx.x;
    float4 va = p[tid], vb = p[tid + 256];
    float v[8] = {va.x, va.y, va.z, va.w, vb.x, vb.y, vb.z, vb.w};
    float m = v[0];
#pragma unroll
    for (int i = 1; i < 8; i++) m = fmaxf(m, v[i]);
#pragma unroll
    for (int o = 16; o; o >>= 1) m = fmaxf(m, __shfl_xor_sync(0xffffffffu, m, o));
    __shared__ float rmax[8], rsum[8];
    if ((tid & 31) == 0) rmax[tid >> 5] = m;
    __syncthreads();
#pragma unroll
    for (int i = 0; i < 8; i++) m = fmaxf(m, rmax[i]);
    float s = 0.f;
#pragma unroll
    for (int i = 0; i < 8; i++) { v[i] = fexp(v[i] - m); s += v[i]; }
#pragma unroll
    for (int o = 16; o; o >>= 1) s += __shfl_xor_sync(0xffffffffu, s, o);
    if ((tid & 31) == 0) rsum[tid >> 5] = s;
    __syncthreads();
    s = 0.f;
#pragma unroll
    for (int i = 0; i < 8; i++) s += rsum[i];
    float inv = 1.f / s;
    va.x = v[0] * inv; va.y = v[1] * inv; va.z = v[2] * inv; va.w = v[3] * inv;
    vb.x = v[4] * inv; vb.y = v[5] * inv; vb.z = v[6] * inv; vb.w = v[7] * inv;
    p[tid] = va; p[tid + 256] = vb;
}

__global__ void __launch_bounds__(256) ln_relu_k(
    float* __restrict__ h, const float* __restrict__ g, const float* __restrict__ b)
{
    float* p = h + (size_t)blockIdx.x * Cc;
    const int tid = threadIdx.x;
    float v[4];
    float s = 0.f, ss = 0.f;
#pragma unroll
    for (int i = 0; i < 4; i++) {
        v[i] = p[tid + 256 * i];
        s += v[i];
        ss += v[i] * v[i];
    }
#pragma unroll
    for (int o = 16; o; o >>= 1) {
        s  += __shfl_xor_sync(0xffffffffu, s, o);
        ss += __shfl_xor_sync(0xffffffffu, ss, o);
    }
    __shared__ float r1[8], r2[8];
    if ((tid & 31) == 0) { r1[tid >> 5] = s; r2[tid >> 5] = ss; }
    __syncthreads();
    s = 0.f; ss = 0.f;
#pragma unroll
    for (int i = 0; i < 8; i++) { s += r1[i]; ss += r2[i]; }
    float mean = s * (1.f / Cc);
    float var  = ss * (1.f / Cc) - mean * mean;
    float inv  = rsqrtf(var + 1e-5f);
#pragma unroll
    for (int i = 0; i < 4; i++) {
        int c = tid + 256 * i;
        float y = (v[i] - mean) * inv * g[c] + b[c];
        p[c] = fmaxf(y, 0.f);
    }
}

// ---------------------------------------------------------------------------
extern "C" void kernel_launch(void* const* d_in, const int* in_sizes, int n_in,
                              void* d_out, int out_size)
{
    (void)in_sizes; (void)n_in; (void)out_size;
    const float* x       = (const float*)d_in[0];
    const float* lfb     = (const float*)d_in[1];
    const float* theta_w = (const float*)d_in[2];
    const float* theta_b = (const float*)d_in[3];
    const float* phi_w   = (const float*)d_in[4];
    const float* phi_b   = (const float*)d_in[5];
    const float* gi_w    = (const float*)d_in[6];
    const float* gi_b    = (const float*)d_in[7];
    const float* ln_g    = (const float*)d_in[8];
    const float* ln_b    = (const float*)d_in[9];
    const float* fc_w    = (const float*)d_in[10];
    const float* fc_b    = (const float*)d_in[11];
    float* out = (float*)d_out;

    float *P, *giT, *logits, *att, *twT, *pwT, *MtP, *Mt, *vp, *v, *cb;
    cudaGetSymbolAddress((void**)&P,      g_P);
    cudaGetSymbolAddress((void**)&giT,    g_giT);
    cudaGetSymbolAddress((void**)&logits, g_logits);
    cudaGetSymbolAddress((void**)&att,    g_att);
    cudaGetSymbolAddress((void**)&twT,    g_twT);
    cudaGetSymbolAddress((void**)&pwT,    g_pwT);
    cudaGetSymbolAddress((void**)&MtP,    g_MtP);
    cudaGetSymbolAddress((void**)&Mt,     g_Mt);
    cudaGetSymbolAddress((void**)&vp,     g_vp);
    cudaGetSymbolAddress((void**)&v,      g_v);
    cudaGetSymbolAddress((void**)&cb,     g_cb);

    static bool s_init = false;
    static cudaStream_t s1, s2;
    static cudaEvent_t ev0, evC, evL[4], evFin;
    if (!s_init) {
        cudaStreamCreateWithFlags(&s1, cudaStreamNonBlocking);
        cudaStreamCreateWithFlags(&s2, cudaStreamNonBlocking);
        cudaEventCreateWithFlags(&ev0,  cudaEventDisableTiming);
        cudaEventCreateWithFlags(&evC,  cudaEventDisableTiming);
        for (int i = 0; i < 4; i++)
            cudaEventCreateWithFlags(&evL[i], cudaEventDisableTiming);
        cudaEventCreateWithFlags(&evFin, cudaEventDisableTiming);
        s_init = true;
    }

    cudaFuncSetAttribute(gemm_cp<true,  false>,
        cudaFuncAttributeMaxDynamicSharedMemorySize, SMEM_ALL);
    cudaFuncSetAttribute(gemm_cp<false, false>,
        cudaFuncAttributeMaxDynamicSharedMemorySize, SMEM_ALL);
    cudaFuncSetAttribute(gemm_cp<false, true>,
        cudaFuncAttributeMaxDynamicSharedMemorySize, SMEM_ALL);

    dim3 blk(256);

    // fork side streams off the origin stream
    cudaEventRecord(ev0, 0);
    cudaStreamWaitEvent(s1, ev0, 0);
    cudaStreamWaitEvent(s2, ev0, 0);

    // s1: giT[b][c][s] = (lfb @ gi_w^T + gi_b)^T
    gemm_cp<false, true><<<dim3(8, 128, 1), blk, SMEM_ALL, s1>>>(
        lfb, gi_w, gi_b, nullptr, giT, Cc, Cc, Cc, 1.f, 0, 0, 0, 0);

    // s2: v = phi_w^T theta_b ; cb = 32*(lfb.v)
    vker_part<<<dim3(4, 32), blk, 0, s2>>>(theta_b, phi_w, vp);
    vker_red<<<4, blk, 0, s2>>>(vp, v);
    cbias_k<<<Bv * Ss / 8, blk, 0, s2>>>(lfb, v, cb);
    cudaEventRecord(evC, s2);

    // origin: transposes -> Mt (split-K x4) -> reduce -> P
    transpose_k<<<dim3(32, 32), dim3(32, 8)>>>(theta_w, twT);
    transpose_k<<<dim3(32, 32), dim3(32, 8)>>>(phi_w, pwT);
    gemm_cp<true, false><<<dim3(8, 8, 4), blk, SMEM_ALL>>>(
        pwT, twT, nullptr, nullptr, MtP, Cc, 256, Cc, 1.f,
        256, 256, (size_t)Cc * Cc, 0);
    red4_k<<<4096, blk>>>(MtP, Mt);
    gemm_cp<true, false><<<dim3(8, 64, 1), blk, SMEM_ALL>>>(
        x, Mt, nullptr, nullptr, P, Cc, Cc, Cc, 1.f, 0, 0, 0, 0);

    // chunked logits (origin) -> softmax/AV/LN (s1, after giT)
    cudaStreamWaitEvent(0, evC, 0);
    for (int c = 0; c < 4; c++) {
        size_t bo = (size_t)c * 2;   // first batch of chunk
        gemm_cp<true, false><<<dim3(16, 8, 2), blk, SMEM_ALL>>>(
            P + bo * Tt * Cc, lfb + bo * Ss * Cc, cb + bo * Ss, nullptr,
            logits + bo * Tt * Ss, Ss, Cc, Cc, 32.f,
            (size_t)Tt * Cc, (size_t)Ss * Cc, (size_t)Tt * Ss, (size_t)Ss);
        cudaEventRecord(evL[c], 0);
    }
    for (int c = 0; c < 4; c++) {
        size_t bo = (size_t)c * 2;
        cudaStreamWaitEvent(s1, evL[c], 0);
        softmax_k<<<2 * Tt, blk, 0, s1>>>(logits + bo * Tt * Ss);
        gemm_cp<false, false><<<dim3(8, 8, 2), blk, SMEM_ALL, s1>>>(
            logits + bo * Tt * Ss, giT + bo * Cc * Ss, nullptr, nullptr,
            att + bo * Tt * Cc, Cc, Ss, Ss, 1.f,
            (size_t)Tt * Ss, (size_t)Cc * Ss, (size_t)Tt * Cc, 0);
        ln_relu_k<<<2 * Tt, blk, 0, s1>>>(att + bo * Tt * Cc, ln_g, ln_b);
    }
    cudaEventRecord(evFin, s1);

    // origin: fc after everything
    cudaStreamWaitEvent(0, evFin, 0);
    gemm_cp<false, false><<<dim3(8, 64, 1), blk, SMEM_ALL>>>(
        att, fc_w, fc_b, x, out, Cc, Cc, Cc, 1.f, 0, 0, 0, 0);
}